// round 17
// baseline (speedup 1.0000x reference)
#include <cuda_runtime.h>
#include <cstdint>
#include <cstddef>

// Problem constants
constexpr int B_  = 64;
constexpr int T_  = 512;
constexpr int D_  = 300;
constexpr int H_  = 256;
constexpr int G_  = 1024;   // 4*H
constexpr int C_  = 9;
constexpr int NTOK = B_ * T_;          // 32768
constexpr int NC_DIR = 64;             // CTAs per direction in recurrence
constexpr int RTHREADS = 512;

// Output layout: logits [B,T,C], log_likelihood [B], trans [C,C]
constexpr int OFF_LL = NTOK * C_;      // 294912
constexpr int OFF_TR = OFF_LL + B_;    // 294976

// smem strides (bank-conflict engineered)
constexpr int HS_STRIDE = 260;   // h_s: conflict-free mma a-frag loads
constexpr int WR_STRIDE = 24;    // Wr_s: conflict-free mma b-frag loads
constexpr int ZP_STRIDE = 18;

// ---------------- scratch (device globals; no cudaMalloc allowed) -----------
__device__ float g_xz[2][NTOK][G_];          // emb@Wk + b, both dirs
__device__ float g_hs[2][B_][T_][H_];        // LSTM hidden outputs
__device__ __align__(16) unsigned g_flag[2][64];  // per-CTA arrival flags
__device__ unsigned g_go[2];                      // broadcast go words

// ---------------- kernel 0: reset barrier state ------------------------------
__global__ void bilstm_init_kernel() {
    int i = threadIdx.x;
    if (i < 64) { g_flag[0][i] = 0u; g_flag[1][i] = 0u; }
    if (i < 2) g_go[i] = 0u;
}

// ---------------- tf32 mma helpers ------------------------------------------
__device__ __forceinline__ unsigned f2tf(float f) {
    unsigned u;
    asm("cvt.rna.tf32.f32 %0, %1;" : "=r"(u) : "f"(f));
    return u;
}
__device__ __forceinline__ float f2tf_f(float f) {
    return __uint_as_float(f2tf(f));
}
__device__ __forceinline__ void mma_tf32(float c[4], const unsigned a[4], const unsigned b[2]) {
    asm volatile(
        "mma.sync.aligned.m16n8k8.row.col.f32.tf32.tf32.f32 "
        "{%0,%1,%2,%3}, {%4,%5,%6,%7}, {%8,%9}, {%0,%1,%2,%3};"
        : "+f"(c[0]), "+f"(c[1]), "+f"(c[2]), "+f"(c[3])
        : "r"(a[0]), "r"(a[1]), "r"(a[2]), "r"(a[3]), "r"(b[0]), "r"(b[1]));
}

// ---------------- kernel 1: fused embedding gather + input GEMM (tf32 HMMA) --
// smem tiles hold PRE-ROUNDED tf32 values; inner loop is pure LDS + HMMA.
__global__ void __launch_bounds__(128)
bilstm_xz_gemm_kernel(const int* __restrict__ inputs,
                      const int* __restrict__ lengths,
                      const float* __restrict__ emb,
                      const float* __restrict__ Wk_f, const float* __restrict__ b_f,
                      const float* __restrict__ Wk_b, const float* __restrict__ b_b)
{
    __shared__ __align__(16) float As[64 * 20];
    __shared__ __align__(16) float Bs[16 * 72];

    const int m0 = blockIdx.y * 64;
    {   // skip tiles where every token is masked: values never used downstream
        const int bb = m0 >> 9;
        const int t0 = m0 & 511;
        if (t0 >= lengths[bb]) return;
    }

    const int dir = blockIdx.z;
    const float* Wk   = dir ? Wk_b : Wk_f;
    const float* bias = dir ? b_b  : b_f;
    const int n0 = blockIdx.x * 64;
    const int tid  = threadIdx.x;
    const int lane = tid & 31;
    const int wid  = tid >> 5;

    const int lm = tid >> 1, kq = (tid & 1) * 8;
    const int kr = tid >> 3, nq = (tid & 7) * 8;
    const int mw = (wid & 1) * 32, nw = (wid >> 1) * 32;
    const int g = lane >> 2, q = lane & 3;

    const int tok = inputs[m0 + lm];
    const float* arow = emb + (size_t)tok * D_;

    float acc[2][4][4];
#pragma unroll
    for (int mi = 0; mi < 2; mi++)
#pragma unroll
        for (int ni = 0; ni < 4; ni++)
#pragma unroll
            for (int e = 0; e < 4; e++) acc[mi][ni][e] = 0.f;

    for (int k0 = 0; k0 < 304; k0 += 16) {
        const bool full = (k0 + 16 <= D_);
        {   // A tile: gather + round to tf32 at staging
            float* dst = As + lm * 20 + kq;
            const int kk = k0 + kq;
            if (full) {
                float4 v0 = *(const float4*)(arow + kk);
                float4 v1 = *(const float4*)(arow + kk + 4);
                dst[0] = f2tf_f(v0.x); dst[1] = f2tf_f(v0.y);
                dst[2] = f2tf_f(v0.z); dst[3] = f2tf_f(v0.w);
                dst[4] = f2tf_f(v1.x); dst[5] = f2tf_f(v1.y);
                dst[6] = f2tf_f(v1.z); dst[7] = f2tf_f(v1.w);
            } else {
#pragma unroll
                for (int e = 0; e < 8; e++)
                    dst[e] = (kk + e < D_) ? f2tf_f(arow[kk + e]) : 0.f;
            }
        }
        {   // B tile: round to tf32 at staging
            float* dst = Bs + kr * 72 + nq;
            const float* src = Wk + (size_t)(k0 + kr) * G_ + n0 + nq;
            if (full || (k0 + kr < D_)) {
                float4 v0 = *(const float4*)(src);
                float4 v1 = *(const float4*)(src + 4);
                dst[0] = f2tf_f(v0.x); dst[1] = f2tf_f(v0.y);
                dst[2] = f2tf_f(v0.z); dst[3] = f2tf_f(v0.w);
                dst[4] = f2tf_f(v1.x); dst[5] = f2tf_f(v1.y);
                dst[6] = f2tf_f(v1.z); dst[7] = f2tf_f(v1.w);
            } else {
                *(float4*)(dst)     = make_float4(0.f, 0.f, 0.f, 0.f);
                *(float4*)(dst + 4) = make_float4(0.f, 0.f, 0.f, 0.f);
            }
        }
        __syncthreads();

#pragma unroll
        for (int kb = 0; kb < 16; kb += 8) {
            unsigned af[2][4], bf[4][2];
#pragma unroll
            for (int mi = 0; mi < 2; mi++) {
                const unsigned* ap = (const unsigned*)As + (mw + mi * 16 + g) * 20 + kb + q;
                af[mi][0] = ap[0];
                af[mi][1] = ap[8 * 20];
                af[mi][2] = ap[4];
                af[mi][3] = ap[8 * 20 + 4];
            }
#pragma unroll
            for (int ni = 0; ni < 4; ni++) {
                const unsigned* bp = (const unsigned*)Bs + (kb + q) * 72 + nw + ni * 8 + g;
                bf[ni][0] = bp[0];
                bf[ni][1] = bp[4 * 72];
            }
#pragma unroll
            for (int mi = 0; mi < 2; mi++)
#pragma unroll
                for (int ni = 0; ni < 4; ni++)
                    mma_tf32(acc[mi][ni], af[mi], bf[ni]);
        }
        __syncthreads();
    }

    float* outp = &g_xz[dir][0][0];
#pragma unroll
    for (int mi = 0; mi < 2; mi++) {
        const int r = m0 + mw + mi * 16 + g;
#pragma unroll
        for (int ni = 0; ni < 4; ni++) {
            const int cc = n0 + nw + ni * 8 + q * 2;
            float2 bv = *(const float2*)(bias + cc);
            float2 o0, o1;
            o0.x = acc[mi][ni][0] + bv.x; o0.y = acc[mi][ni][1] + bv.y;
            o1.x = acc[mi][ni][2] + bv.x; o1.y = acc[mi][ni][3] + bv.y;
            *(float2*)(outp + (size_t)r * G_ + cc)       = o0;
            *(float2*)(outp + (size_t)(r + 8) * G_ + cc) = o1;
        }
    }
}

// ---------------- kernel 2: persistent bidirectional LSTM (tf32 HMMA GEMV) --
// 128 CTAs (0..63 fwd, 64..127 bwd), 512 threads. CTA (dir,j) owns hidden cols
// [4j,4j+4). Per step: tensor-core GEMV, gates, hs store, then an atomic-free
// flag barrier: per-CTA release-store flags -> detector CTA sweeps flags with
// v4 acquire loads -> release-store broadcast 'go' -> others poll 'go'.
__global__ void __launch_bounds__(RTHREADS, 1)
bilstm_lstm_kernel(const float* __restrict__ Wr_f,
                   const float* __restrict__ Wr_b,
                   const int* __restrict__ lengths)
{
    extern __shared__ __align__(16) float smem[];
    float* Wr_s = smem;                      // 256*24 = 6144  (tf32-rounded)
    float* h_s  = Wr_s + 6144;               // 64*260 = 16640 (tf32-rounded)
    float* zp   = h_s + 16640;               // 2*64*18 = 2304
    float* c_s  = zp + 2304;                 // 256
    int*   len_s = (int*)(c_s + 256);        // 64

    const int tid = threadIdx.x;
    const int dir = blockIdx.x >> 6;
    const int j   = blockIdx.x & 63;
    const float* Wr  = dir ? Wr_b : Wr_f;
    const float* xzp = &g_xz[dir][0][0];
    float* hsp = &g_hs[dir][0][0][0];

    // prologue (Wr rounded to tf32 once, here)
    for (int idx = tid; idx < 4096; idx += RTHREADS) {
        int k = idx >> 4, gi = idx & 15;
        int gate = gi >> 2, cc = gi & 3;
        Wr_s[k * WR_STRIDE + gi] = f2tf_f(Wr[(size_t)k * G_ + gate * H_ + j*4 + cc]);
    }
    for (int idx = tid; idx < 64 * HS_STRIDE; idx += RTHREADS) h_s[idx] = 0.f;
    if (tid < 256) c_s[tid] = 0.f;
    if (tid < 64)  len_s[tid] = lengths[tid];
    __syncthreads();

    // mma warp mapping: 16 warps = 4 m-tiles x 2 n-tiles x 2 k-halves
    const int wid = tid >> 5, lane = tid & 31;
    const int g = lane >> 2, q = lane & 3;
    const int m0w = (wid & 3) * 16;
    const int n0w = ((wid >> 2) & 1) * 8;
    const int kh  = wid >> 3;
    const unsigned* aB = (const unsigned*)h_s + (m0w + g) * HS_STRIDE + kh * 128 + q;
    const unsigned* bB = (const unsigned*)Wr_s + (kh * 128 + q) * WR_STRIDE + n0w + g;
    float* zpw = zp + kh * (64 * ZP_STRIDE) + n0w + 2 * q;

    // gate-phase mapping (tid < 256)
    const int gb = tid >> 2, gc = tid & 3;
    const int hc = j*4 + gc;

    unsigned* flagp = &g_flag[dir][j];
    unsigned* gop   = &g_go[dir];

    for (int s = 0; s < T_; s++) {
        const int tt = dir ? (T_ - 1 - s) : s;

        // prefetch xz for this step (DRAM latency hidden behind the mma loop)
        float xz0 = 0.f, xz1 = 0.f, xz2 = 0.f, xz3 = 0.f;
        if (tid < 256) {
            const float* xb = xzp + (size_t)(gb * T_ + tt) * G_ + hc;
            xz0 = xb[0]; xz1 = xb[H_]; xz2 = xb[2*H_]; xz3 = xb[3*H_];
        }

        // ---- z partial = h_prev @ Wr_slice  (two independent mma chains)
        float c0[4] = {0.f, 0.f, 0.f, 0.f};
        float c1[4] = {0.f, 0.f, 0.f, 0.f};
#pragma unroll
        for (int kk = 0; kk < 128; kk += 16) {
            unsigned af[4], bf[2];
            af[0] = aB[kk];     af[1] = aB[kk + 8 * HS_STRIDE];
            af[2] = aB[kk + 4]; af[3] = aB[kk + 4 + 8 * HS_STRIDE];
            bf[0] = bB[kk * WR_STRIDE];
            bf[1] = bB[(kk + 4) * WR_STRIDE];
            mma_tf32(c0, af, bf);
            af[0] = aB[kk + 8];  af[1] = aB[kk + 8 + 8 * HS_STRIDE];
            af[2] = aB[kk + 12]; af[3] = aB[kk + 12 + 8 * HS_STRIDE];
            bf[0] = bB[(kk + 8) * WR_STRIDE];
            bf[1] = bB[(kk + 12) * WR_STRIDE];
            mma_tf32(c1, af, bf);
        }
        c0[0] += c1[0]; c0[1] += c1[1]; c0[2] += c1[2]; c0[3] += c1[3];
        *(float2*)(zpw + (m0w + g) * ZP_STRIDE)     = make_float2(c0[0], c0[1]);
        *(float2*)(zpw + (m0w + g + 8) * ZP_STRIDE) = make_float2(c0[2], c0[3]);
        __syncthreads();

        // ---- gate phase
        if (tid < 256) {
            const float* z0 = zp + gb * ZP_STRIDE;
            const float* z1 = z0 + 64 * ZP_STRIDE;
            float zi = z0[gc]      + z1[gc]      + xz0;
            float zf = z0[4 + gc]  + z1[4 + gc]  + xz1;
            float zg = z0[8 + gc]  + z1[8 + gc]  + xz2;
            float zo = z0[12 + gc] + z1[12 + gc] + xz3;
            float ig = 1.f / (1.f + expf(-zi));
            float fg = 1.f / (1.f + expf(-zf));
            float gg = tanhf(zg);
            float og_ = 1.f / (1.f + expf(-zo));
            float cold = c_s[tid];
            float cn = fg * cold + ig * gg;
            float hn = og_ * tanhf(cn);
            bool mv = (tt < len_s[gb]);
            float hout = mv ? hn : h_s[gb * HS_STRIDE + hc];
            if (mv) c_s[tid] = cn;
            hsp[(size_t)(gb * T_ + tt) * H_ + hc] = hout;
        }

        if (s == T_ - 1) break;          // last step: no consumer, skip barrier
        __syncthreads();                 // hs writes CTA-complete before release

        // ---- atomic-free grid barrier for this direction
        const unsigned tgt = (unsigned)(s + 1);
        if (tid == 0)
            asm volatile("st.release.gpu.global.u32 [%0], %1;"
                         :: "l"(flagp), "r"(tgt) : "memory");
        if (j == 0) {
            if (tid < 16) {               // detector: sweep all 64 flags
                const unsigned* fp = &g_flag[dir][tid * 4];
                for (;;) {
                    unsigned v0, v1, v2, v3;
                    asm volatile("ld.acquire.gpu.global.v4.u32 {%0,%1,%2,%3}, [%4];"
                                 : "=r"(v0), "=r"(v1), "=r"(v2), "=r"(v3)
                                 : "l"(fp) : "memory");
                    if (v0 >= tgt && v1 >= tgt && v2 >= tgt && v3 >= tgt) break;
                }
                __syncwarp(0x0000ffffu);
                if (tid == 0)
                    asm volatile("st.release.gpu.global.u32 [%0], %1;"
                                 :: "l"(gop), "r"(tgt) : "memory");
            }
        } else if (tid == 0) {            // waiters: poll broadcast word only
            unsigned v;
            do {
                asm volatile("ld.acquire.gpu.global.u32 %0, [%1];"
                             : "=r"(v) : "l"(gop) : "memory");
            } while (v < tgt);
        }
        __syncthreads();

        // ---- reload h for next step (round to tf32 at staging)
        {
            int lb = tid >> 3, kp = tid & 7;
            const float4* src = (const float4*)(hsp + (size_t)(lb * T_ + tt) * H_);
            float* dst = h_s + lb * HS_STRIDE;
#pragma unroll
            for (int ii = 0; ii < 8; ii++) {
                float4 v = src[ii * 8 + kp];
                int kb = ii * 32 + kp * 4;
                dst[kb + 0] = f2tf_f(v.x); dst[kb + 1] = f2tf_f(v.y);
                dst[kb + 2] = f2tf_f(v.z); dst[kb + 3] = f2tf_f(v.w);
            }
        }
        __syncthreads();
    }
}

// ---------------- kernel 3: dense projection to logits -----------------------
constexpr int DTOK = 16;
__global__ void __launch_bounds__(160)
bilstm_dense_kernel(const float* __restrict__ W, const float* __restrict__ bias,
                    float* __restrict__ out)
{
    __shared__ __align__(16) float hsm[DTOK * 513];
    const int tid = threadIdx.x;
    const int tok0 = blockIdx.x * DTOK;

    for (int idx = tid; idx < DTOK * 512; idx += 160) {
        int tk = idx >> 9, k = idx & 511;
        int tg = tok0 + tk;
        int b = tg >> 9, t = tg & 511;
        float v = (k < H_) ? g_hs[0][b][t][k] : g_hs[1][b][t][k - H_];
        hsm[tk * 513 + k] = v;
    }
    __syncthreads();

    if (tid < DTOK * C_) {
        int tk = tid / C_, c = tid % C_;
        float acc = bias[c];
        const float* hr = hsm + tk * 513;
#pragma unroll 8
        for (int k = 0; k < 512; k++) acc += hr[k] * W[k * C_ + c];
        out[(size_t)(tok0 + tk) * C_ + c] = acc;
    }
}

// ---------------- kernel 4: CRF log-likelihood + trans copy -----------------
__global__ void __launch_bounds__(32)
bilstm_crf_kernel(const float* __restrict__ logits,
                  const int* __restrict__ targets,
                  const int* __restrict__ lengths,
                  const float* __restrict__ trans,
                  float* __restrict__ out_ll, float* __restrict__ out_trans)
{
    __shared__ float tr[81];
    __shared__ float alpha[16];
    const int b = blockIdx.x;
    const int lane = threadIdx.x;

    for (int i = lane; i < 81; i += 32) tr[i] = trans[i];
    if (b == 0)
        for (int i = lane; i < 81; i += 32) out_trans[i] = trans[i];
    __syncwarp();

    const int len = lengths[b];
    const float* lg = logits + (size_t)b * T_ * C_;
    const int* tg = targets + b * T_;

    float us = 0.f, bs = 0.f;
    for (int t = lane; t < T_; t += 32) {
        if (t < len)     us += lg[t * C_ + tg[t]];
        if (t < len - 1) bs += tr[tg[t] * C_ + tg[t + 1]];
    }
#pragma unroll
    for (int off = 16; off; off >>= 1) {
        us += __shfl_xor_sync(0xffffffffu, us, off);
        bs += __shfl_xor_sync(0xffffffffu, bs, off);
    }

    if (lane < C_) alpha[lane] = lg[lane];
    __syncwarp();
    for (int t = 1; t < len; t++) {
        float a_new = 0.f;
        if (lane < C_) {
            float v[C_];
            float m = -1e30f;
#pragma unroll
            for (int c = 0; c < C_; c++) {
                v[c] = alpha[c] + tr[c * C_ + lane];
                m = fmaxf(m, v[c]);
            }
            float ssum = 0.f;
#pragma unroll
            for (int c = 0; c < C_; c++) ssum += expf(v[c] - m);
            a_new = m + logf(ssum) + lg[t * C_ + lane];
        }
        __syncwarp();
        if (lane < C_) alpha[lane] = a_new;
        __syncwarp();
    }

    if (lane == 0) {
        float m = -1e30f;
        for (int c = 0; c < C_; c++) m = fmaxf(m, alpha[c]);
        float ssum = 0.f;
        for (int c = 0; c < C_; c++) ssum += expf(alpha[c] - m);
        out_ll[b] = us + bs - (m + logf(ssum));
    }
}

// ---------------- launch ------------------------------------------------------
extern "C" void kernel_launch(void* const* d_in, const int* in_sizes, int n_in,
                              void* d_out, int out_size) {
    (void)in_sizes; (void)n_in; (void)out_size;
    const int*   inputs  = (const int*)  d_in[0];
    const int*   lengths = (const int*)  d_in[1];
    const int*   targets = (const int*)  d_in[2];
    const float* emb     = (const float*)d_in[3];
    const float* Wk_f    = (const float*)d_in[4];
    const float* Wr_f    = (const float*)d_in[5];
    const float* b_f     = (const float*)d_in[6];
    const float* Wk_b    = (const float*)d_in[7];
    const float* Wr_b    = (const float*)d_in[8];
    const float* b_b     = (const float*)d_in[9];
    const float* dW      = (const float*)d_in[10];
    const float* db      = (const float*)d_in[11];
    const float* trans   = (const float*)d_in[12];
    float* out = (float*)d_out;

    const int lstm_smem = (6144 + 16640 + 2304 + 256) * 4 + 64 * 4;  // 101632 B
    cudaFuncSetAttribute(bilstm_lstm_kernel,
                         cudaFuncAttributeMaxDynamicSharedMemorySize, lstm_smem);

    bilstm_init_kernel<<<1, 64>>>();

    dim3 gA(G_ / 64, NTOK / 64, 2);
    bilstm_xz_gemm_kernel<<<gA, 128>>>(inputs, lengths, emb, Wk_f, b_f, Wk_b, b_b);

    bilstm_lstm_kernel<<<2 * NC_DIR, RTHREADS, lstm_smem>>>(Wr_f, Wr_b, lengths);

    bilstm_dense_kernel<<<NTOK / DTOK, 160>>>(dW, db, out);

    bilstm_crf_kernel<<<B_, 32>>>(out, targets, lengths, trans,
                                  out + OFF_LL, out + OFF_TR);
}